// round 1
// baseline (speedup 1.0000x reference)
#include <cuda_runtime.h>
#include <cstdint>

// Problem constants
#define BATCH  8
#define CIN    192
#define NPIX   4096
#define OPROJ  288     // 3 * LATENT
#define LAT    96

// Scratch (module-static device memory; allocation-free)
__device__ float g_t[BATCH * OPROJ * NPIX];     // rows 0-95: Q, 96-191: V, 192-287: K
__device__ float g_att[BATCH * LAT * NPIX];     // attention output (pre output-proj)

// ---------------------------------------------------------------------------
// helpers
// ---------------------------------------------------------------------------
__device__ __forceinline__ float tf32r(float x) {
    uint32_t u;
    asm("cvt.rna.tf32.f32 %0, %1;" : "=r"(u) : "f"(x));
    return __uint_as_float(u);
}

__device__ __forceinline__ void mma8(float d[4], const uint32_t a[4], const uint32_t b[2]) {
    asm volatile(
        "mma.sync.aligned.m16n8k8.row.col.f32.tf32.tf32.f32 "
        "{%0,%1,%2,%3}, {%4,%5,%6,%7}, {%8,%9}, {%0,%1,%2,%3};"
        : "+f"(d[0]), "+f"(d[1]), "+f"(d[2]), "+f"(d[3])
        : "r"(a[0]), "r"(a[1]), "r"(a[2]), "r"(a[3]), "r"(b[0]), "r"(b[1]));
}

// ---------------------------------------------------------------------------
// Kernel 1: t[b,o,n] = sum_c Wt[o,c] * x[b,c,n] + bt[o]
// grid (32 n-tiles, 3 o-tiles of 96, 8 batch), 256 threads
// CTA tile: 96 (o) x 128 (n), K-tile 16. fp32 SIMT.
// ---------------------------------------------------------------------------
__global__ __launch_bounds__(256) void proj_kernel(
    const float* __restrict__ x, const float* __restrict__ Wt,
    const float* __restrict__ bt)
{
    __shared__ float sW[96][17];
    __shared__ float sX[16][128];

    const int b  = blockIdx.z;
    const int o0 = blockIdx.y * 96;
    const int n0 = blockIdx.x * 128;
    const int tid = threadIdx.x;
    const int ty = tid >> 4;      // 0..15
    const int tx = tid & 15;      // 0..15

    float acc[6][8];
    #pragma unroll
    for (int i = 0; i < 6; i++)
        #pragma unroll
        for (int j = 0; j < 8; j++) acc[i][j] = 0.f;

    for (int k0 = 0; k0 < CIN; k0 += 16) {
        // load Wt tile 96x16
        #pragma unroll
        for (int it = 0; it < 6; it++) {
            int idx = tid + it * 256;         // 0..1535
            int r = idx >> 4, c = idx & 15;
            sW[r][c] = Wt[(o0 + r) * CIN + k0 + c];
        }
        // load x tile 16x128 (float4)
        #pragma unroll
        for (int it = 0; it < 2; it++) {
            int idx = tid + it * 256;         // 0..511 float4 units
            int r = idx >> 5, c4 = idx & 31;
            float4 v = *reinterpret_cast<const float4*>(
                x + ((size_t)(b * CIN + k0 + r)) * NPIX + n0 + c4 * 4);
            *reinterpret_cast<float4*>(&sX[r][c4 * 4]) = v;
        }
        __syncthreads();

        #pragma unroll
        for (int kk = 0; kk < 16; kk++) {
            float a[6], bb[8];
            #pragma unroll
            for (int i = 0; i < 6; i++) a[i] = sW[ty + 16 * i][kk];
            #pragma unroll
            for (int j = 0; j < 8; j++) bb[j] = sX[kk][tx + 16 * j];
            #pragma unroll
            for (int i = 0; i < 6; i++)
                #pragma unroll
                for (int j = 0; j < 8; j++)
                    acc[i][j] = fmaf(a[i], bb[j], acc[i][j]);
        }
        __syncthreads();
    }

    #pragma unroll
    for (int i = 0; i < 6; i++) {
        int o = o0 + ty + 16 * i;
        float bias = bt[o];
        #pragma unroll
        for (int j = 0; j < 8; j++) {
            int n = n0 + tx + 16 * j;
            g_t[((size_t)(b * OPROJ + o)) * NPIX + n] = acc[i][j] + bias;
        }
    }
}

// ---------------------------------------------------------------------------
// Kernel 2: fused flash attention (tf32 mma, fp32 softmax)
//   out_att[b,c,k] = sum_q V[b,c,q] * softmax_q( (Q[:,q]. K[:,k]) / sqrt(96) )
// grid (32 k-blocks of 128, 8 batch), 256 threads (8 warps), 1 CTA/SM.
// ---------------------------------------------------------------------------
#define RK 136      // padded row length for sK/sQ  (136 % 32 == 8  -> conflict-free (8t+g))
#define RV 132      // padded row length for sV/sP  (132 % 32 == 4  -> conflict-free (4g+t))
#define OFF_K 0
#define OFF_Q (96 * RK)                 // 13056
#define OFF_V (OFF_Q + 96 * RK)         // 26112
#define OFF_P (OFF_V + 96 * RV)         // 38784
#define OFF_M (OFF_P + 128 * RV)        // 55680
#define OFF_L (OFF_M + 128)
#define OFF_A (OFF_L + 128)
#define OFF_T (OFF_A + 128)
#define ATTN_SMEM_FLOATS (OFF_T + 256)  // 56320
#define ATTN_SMEM_BYTES (ATTN_SMEM_FLOATS * 4)

__global__ __launch_bounds__(256, 1) void attn_kernel()
{
    extern __shared__ float sm[];
    float* sK = sm + OFF_K;
    float* sQ = sm + OFF_Q;
    float* sV = sm + OFF_V;
    float* sP = sm + OFF_P;
    float* sM = sm + OFF_M;
    float* sL = sm + OFF_L;
    float* sA = sm + OFF_A;
    float* sT = sm + OFF_T;

    const int b  = blockIdx.y;
    const int k0 = blockIdx.x * 128;
    const int tid  = threadIdx.x;
    const int warp = tid >> 5;
    const int lane = tid & 31;
    const int g = lane >> 2;     // 0..7
    const int t = lane & 3;      // 0..3
    const int wm = warp >> 2;    // 0..1
    const int wn = warp & 3;     // 0..3

    const float invRDK = 0.10206207261596575f;   // 1/sqrt(96)

    const float* __restrict__ Qg = g_t + ((size_t)(b * OPROJ +   0)) * NPIX;
    const float* __restrict__ Vg = g_t + ((size_t)(b * OPROJ +  96)) * NPIX;
    const float* __restrict__ Kg = g_t + ((size_t)(b * OPROJ + 192)) * NPIX;

    // stage K block (scaled + tf32-rounded), 96 x 128
    for (int idx = tid; idx < 96 * 32; idx += 256) {
        int c = idx >> 5, i4 = (idx & 31) * 4;
        float4 v = *reinterpret_cast<const float4*>(Kg + (size_t)c * NPIX + k0 + i4);
        v.x = tf32r(v.x * invRDK); v.y = tf32r(v.y * invRDK);
        v.z = tf32r(v.z * invRDK); v.w = tf32r(v.w * invRDK);
        *reinterpret_cast<float4*>(&sK[c * RK + i4]) = v;
    }
    if (tid < 128) { sM[tid] = -1e30f; sL[tid] = 0.f; }

    // O accumulator: 96 (c) x 128 (kq) distributed; this thread holds 3x4x4
    float O[3][4][4];
    #pragma unroll
    for (int mi = 0; mi < 3; mi++)
        #pragma unroll
        for (int ni = 0; ni < 4; ni++)
            #pragma unroll
            for (int r = 0; r < 4; r++) O[mi][ni][r] = 0.f;

    const uint32_t* Ku = reinterpret_cast<const uint32_t*>(sK);
    const uint32_t* Qu = reinterpret_cast<const uint32_t*>(sQ);
    const uint32_t* Vu = reinterpret_cast<const uint32_t*>(sV);
    const uint32_t* Pu = reinterpret_cast<const uint32_t*>(sP);

    for (int q0 = 0; q0 < NPIX; q0 += 128) {
        // stage Q and V tiles (tf32-rounded)
        for (int idx = tid; idx < 96 * 32; idx += 256) {
            int c = idx >> 5, i4 = (idx & 31) * 4;
            float4 q = *reinterpret_cast<const float4*>(Qg + (size_t)c * NPIX + q0 + i4);
            q.x = tf32r(q.x); q.y = tf32r(q.y); q.z = tf32r(q.z); q.w = tf32r(q.w);
            *reinterpret_cast<float4*>(&sQ[c * RK + i4]) = q;
            float4 v = *reinterpret_cast<const float4*>(Vg + (size_t)c * NPIX + q0 + i4);
            v.x = tf32r(v.x); v.y = tf32r(v.y); v.z = tf32r(v.z); v.w = tf32r(v.w);
            *reinterpret_cast<float4*>(&sV[c * RV + i4]) = v;
        }
        __syncthreads();

        // ---- GEMM1: S[i(kq), j(q)] = sum_c K[c,i] * Q[c,j]  (128x128, k=96) ----
        float S[4][4][4];
        #pragma unroll
        for (int mi = 0; mi < 4; mi++)
            #pragma unroll
            for (int ni = 0; ni < 4; ni++)
                #pragma unroll
                for (int r = 0; r < 4; r++) S[mi][ni][r] = 0.f;

        #pragma unroll
        for (int cs = 0; cs < 96; cs += 8) {
            uint32_t A[4][4], B[4][2];
            #pragma unroll
            for (int mi = 0; mi < 4; mi++) {
                int rr = wm * 64 + mi * 16 + g;
                A[mi][0] = Ku[(cs + t) * RK + rr];
                A[mi][1] = Ku[(cs + t) * RK + rr + 8];
                A[mi][2] = Ku[(cs + t + 4) * RK + rr];
                A[mi][3] = Ku[(cs + t + 4) * RK + rr + 8];
            }
            #pragma unroll
            for (int ni = 0; ni < 4; ni++) {
                int cc = wn * 32 + ni * 8 + g;
                B[ni][0] = Qu[(cs + t) * RK + cc];
                B[ni][1] = Qu[(cs + t + 4) * RK + cc];
            }
            #pragma unroll
            for (int mi = 0; mi < 4; mi++)
                #pragma unroll
                for (int ni = 0; ni < 4; ni++)
                    mma8(S[mi][ni], A[mi], B[ni]);
        }

        // store S -> sP
        #pragma unroll
        for (int mi = 0; mi < 4; mi++) {
            int i = wm * 64 + mi * 16 + g;
            #pragma unroll
            for (int ni = 0; ni < 4; ni++) {
                int j = wn * 32 + ni * 8 + 2 * t;
                sP[i * RV + j]           = S[mi][ni][0];
                sP[i * RV + j + 1]       = S[mi][ni][1];
                sP[(i + 8) * RV + j]     = S[mi][ni][2];
                sP[(i + 8) * RV + j + 1] = S[mi][ni][3];
            }
        }
        __syncthreads();

        // ---- online softmax over rows of sP ----
        const int r  = tid & 127;
        const int h  = tid >> 7;
        float4* rowp = reinterpret_cast<float4*>(sP + r * RV + h * 64);

        float lmax = -1e30f;
        #pragma unroll
        for (int u = 0; u < 16; u++) {
            float4 v = rowp[u];
            lmax = fmaxf(lmax, fmaxf(fmaxf(v.x, v.y), fmaxf(v.z, v.w)));
        }
        sT[tid] = lmax;
        __syncthreads();
        if (tid < 128) {
            float mt = fmaxf(sT[tid], sT[tid + 128]);
            float mo = sM[tid];
            float mn = fmaxf(mo, mt);
            sA[tid] = __expf(mo - mn);
            sM[tid] = mn;
        }
        __syncthreads();

        float mn = sM[r];
        float lsum = 0.f;
        #pragma unroll
        for (int u = 0; u < 16; u++) {
            float4 v = rowp[u];
            v.x = tf32r(__expf(v.x - mn));
            v.y = tf32r(__expf(v.y - mn));
            v.z = tf32r(__expf(v.z - mn));
            v.w = tf32r(__expf(v.w - mn));
            lsum += v.x + v.y + v.z + v.w;
            rowp[u] = v;
        }
        sT[tid] = lsum;

        // rescale O by alpha (per kq column)
        #pragma unroll
        for (int ni = 0; ni < 4; ni++) {
            int base = wn * 32 + ni * 8 + 2 * t;
            float ae = sA[base], ao = sA[base + 1];
            #pragma unroll
            for (int mi = 0; mi < 3; mi++) {
                O[mi][ni][0] *= ae; O[mi][ni][1] *= ao;
                O[mi][ni][2] *= ae; O[mi][ni][3] *= ao;
            }
        }
        __syncthreads();
        if (tid < 128) sL[tid] = sL[tid] * sA[tid] + sT[tid] + sT[tid + 128];

        // ---- GEMM2: O[c, kq] += sum_q V[c,q] * P[kq,q]  (96x128, k=128) ----
        #pragma unroll
        for (int qs = 0; qs < 128; qs += 8) {
            uint32_t A[3][4], B[4][2];
            #pragma unroll
            for (int mi = 0; mi < 3; mi++) {
                int rr = wm * 48 + mi * 16 + g;
                A[mi][0] = Vu[rr * RV + qs + t];
                A[mi][1] = Vu[(rr + 8) * RV + qs + t];
                A[mi][2] = Vu[rr * RV + qs + t + 4];
                A[mi][3] = Vu[(rr + 8) * RV + qs + t + 4];
            }
            #pragma unroll
            for (int ni = 0; ni < 4; ni++) {
                int cc = wn * 32 + ni * 8 + g;
                B[ni][0] = Pu[cc * RV + qs + t];
                B[ni][1] = Pu[cc * RV + qs + t + 4];
            }
            #pragma unroll
            for (int mi = 0; mi < 3; mi++)
                #pragma unroll
                for (int ni = 0; ni < 4; ni++)
                    mma8(O[mi][ni], A[mi], B[ni]);
        }
        __syncthreads();
    }

    // epilogue: normalize by l, write to g_att
    #pragma unroll
    for (int mi = 0; mi < 3; mi++) {
        int c = wm * 48 + mi * 16 + g;
        #pragma unroll
        for (int ni = 0; ni < 4; ni++) {
            int kq = wn * 32 + ni * 8 + 2 * t;
            float le = sL[kq], lo = sL[kq + 1];
            size_t base = ((size_t)(b * LAT + c)) * NPIX + k0 + kq;
            g_att[base]                = O[mi][ni][0] / le;
            g_att[base + 1]            = O[mi][ni][1] / lo;
            g_att[base + 8 * NPIX]     = O[mi][ni][2] / le;
            g_att[base + 8 * NPIX + 1] = O[mi][ni][3] / lo;
        }
    }
}

// ---------------------------------------------------------------------------
// Kernel 3: out[b,o,n] = x[b,o,n] + bd[o] + sum_c Wd[o,c] * att[b,c,n]
// grid (32 n-tiles, 3 o-tiles of 64, 8 batch), 256 threads. fp32 SIMT.
// ---------------------------------------------------------------------------
#define OUT_SMEM_FLOATS (64 * 97 + 96 * 128)
#define OUT_SMEM_BYTES (OUT_SMEM_FLOATS * 4)

__global__ __launch_bounds__(256) void outproj_kernel(
    const float* __restrict__ x, const float* __restrict__ Wd,
    const float* __restrict__ bd, float* __restrict__ out)
{
    extern __shared__ float sm[];
    float (*sWd)[97] = reinterpret_cast<float(*)[97]>(sm);
    float (*sAtt)[128] = reinterpret_cast<float(*)[128]>(sm + 64 * 97);

    const int b  = blockIdx.z;
    const int o0 = blockIdx.y * 64;
    const int n0 = blockIdx.x * 128;
    const int tid = threadIdx.x;
    const int ty = tid >> 4, tx = tid & 15;

    for (int idx = tid; idx < 64 * 96; idx += 256) {
        int r = idx / 96, c = idx % 96;
        sWd[r][c] = Wd[(o0 + r) * LAT + c];
    }
    for (int idx = tid; idx < 96 * 32; idx += 256) {
        int r = idx >> 5, c4 = (idx & 31) * 4;
        float4 v = *reinterpret_cast<const float4*>(
            g_att + ((size_t)(b * LAT + r)) * NPIX + n0 + c4);
        *reinterpret_cast<float4*>(&sAtt[r][c4]) = v;
    }
    __syncthreads();

    float acc[4][8];
    #pragma unroll
    for (int i = 0; i < 4; i++)
        #pragma unroll
        for (int j = 0; j < 8; j++) acc[i][j] = 0.f;

    #pragma unroll 4
    for (int c = 0; c < 96; c++) {
        float a[4], bb[8];
        #pragma unroll
        for (int i = 0; i < 4; i++) a[i] = sWd[ty + 16 * i][c];
        #pragma unroll
        for (int j = 0; j < 8; j++) bb[j] = sAtt[c][tx + 16 * j];
        #pragma unroll
        for (int i = 0; i < 4; i++)
            #pragma unroll
            for (int j = 0; j < 8; j++)
                acc[i][j] = fmaf(a[i], bb[j], acc[i][j]);
    }

    #pragma unroll
    for (int i = 0; i < 4; i++) {
        int o = o0 + ty + 16 * i;
        float bias = bd[o];
        #pragma unroll
        for (int j = 0; j < 8; j++) {
            int n = n0 + tx + 16 * j;
            size_t idx = ((size_t)(b * CIN + o)) * NPIX + n;
            out[idx] = acc[i][j] + bias + x[idx];
        }
    }
}

// ---------------------------------------------------------------------------
extern "C" void kernel_launch(void* const* d_in, const int* in_sizes, int n_in,
                              void* d_out, int out_size)
{
    const float* x  = (const float*)d_in[0];
    const float* Wt = (const float*)d_in[1];
    const float* bt = (const float*)d_in[2];
    const float* Wd = (const float*)d_in[3];
    const float* bd = (const float*)d_in[4];
    float* out = (float*)d_out;

    cudaFuncSetAttribute(attn_kernel,
        cudaFuncAttributeMaxDynamicSharedMemorySize, ATTN_SMEM_BYTES);
    cudaFuncSetAttribute(outproj_kernel,
        cudaFuncAttributeMaxDynamicSharedMemorySize, OUT_SMEM_BYTES);

    proj_kernel<<<dim3(32, 3, BATCH), 256>>>(x, Wt, bt);
    attn_kernel<<<dim3(32, BATCH), 256, ATTN_SMEM_BYTES>>>();
    outproj_kernel<<<dim3(32, 3, BATCH), 256, OUT_SMEM_BYTES>>>(x, Wd, bd, out);
}